// round 15
// baseline (speedup 1.0000x reference)
#include <cuda_runtime.h>
#include <cstdint>
#include <cfloat>

// Problem constants
#define N_PIX   16777216          // 16 * 1 * 1024 * 1024
#define NF4     4194304           // N_PIX / 4
#define RB      1024              // reduction blocks
#define BINS    256
#define TILES   1024              // 16 images * 8 * 8
#define CLIPV   2560.0f           // max(int(40.0*16384//256),1)
#define FGRID   1024              // fused kernel grid
#define NITEMS  2048              // 1024 hist + 1024 apply

// Scratch (device globals only — no allocations allowed)
__device__ float         g_pmin[RB];
__device__ float         g_pmax[RB];
__device__ double        g_psum[RB];
__device__ double        g_psq [RB];
__device__ float         g_AB[2];     // A*256, B*256 (bin-ready affine)
__device__ unsigned int  g_ctr = 0;
__device__ unsigned char g_lut8[TILES * BINS];
__device__ unsigned int  g_qhead = 0;          // work-queue head
__device__ unsigned int  g_qdone = 0;          // exit tickets
__device__ unsigned int  g_rowdone[128];       // (image, tile-row) -> tiles done

__device__ __forceinline__ unsigned int smem_u32(const void* p)
{
    unsigned int a;
    asm("{ .reg .u64 t; cvta.to.shared.u64 t, %1; cvt.u32.u64 %0, t; }"
        : "=r"(a) : "l"(p));
    return a;
}

// L2 access policies: x lines pinned (evict_last), out lines disposable.
__device__ __forceinline__ unsigned long long pol_evict_last()
{
    unsigned long long p;
    asm("createpolicy.fractional.L2::evict_last.b64 %0, 1.0;" : "=l"(p));
    return p;
}
__device__ __forceinline__ unsigned long long pol_evict_first()
{
    unsigned long long p;
    asm("createpolicy.fractional.L2::evict_first.b64 %0, 1.0;" : "=l"(p));
    return p;
}
__device__ __forceinline__ float4 ld_x(const float4* p, unsigned long long pol)
{
    float4 v;
    asm volatile("ld.global.L2::cache_hint.v4.f32 {%0,%1,%2,%3}, [%4], %5;"
                 : "=f"(v.x), "=f"(v.y), "=f"(v.z), "=f"(v.w)
                 : "l"(p), "l"(pol));
    return v;
}
__device__ __forceinline__ void st_out(float4* p, float4 v, unsigned long long pol)
{
    asm volatile("st.global.L2::cache_hint.v4.f32 [%0], {%1,%2,%3,%4}, %5;"
                 :: "l"(p), "f"(v.x), "f"(v.y), "f"(v.z), "f"(v.w), "l"(pol)
                 : "memory");
}

// ---------------------------------------------------------------------------
// Kernel 1: streaming min/max/sum/sumsq, 8-stage cp.async ring (R11-proven),
// with L2 evict_last hints on the x stream so x persists across graph
// replays. Warp-shuffle epilogue; last block folds partials, computes A*256
// and B*256 (fp64 replica of the reference chain), writes the y tail.
// ---------------------------------------------------------------------------
__global__ void __launch_bounds__(256) k_reduce(const float4* __restrict__ x,
                                                const int* __restrict__ y,
                                                float* __restrict__ tail_dst,
                                                int tail_n)
{
    __shared__ float4 sbuf[8 * 256];        // 32 KB ring (8 stages)
    __shared__ float  wmn[8], wmx[8];
    __shared__ double wss[8], wsq[8];

    int tid  = threadIdx.x;
    int lane = tid & 31;
    int wid  = tid >> 5;
    int t    = blockIdx.x * 256 + tid;

    unsigned long long pl = pol_evict_last();

    float mn =  FLT_MAX, mx = -FLT_MAX;
    float s = 0.0f, q = 0.0f;

#define ISSUE(c) { \
        unsigned int dst = smem_u32(&sbuf[((c) & 7) * 256 + tid]); \
        const float4* src = x + t + (c) * (RB * 256); \
        asm volatile("cp.async.cg.shared.global.L2::cache_hint [%0], [%1], 16, %2;" \
                     :: "r"(dst), "l"(src), "l"(pl)); \
        asm volatile("cp.async.commit_group;"); }

#define CONSUME(c, W) { \
        asm volatile("cp.async.wait_group " #W ";" ::: "memory"); \
        float4 v = sbuf[((c) & 7) * 256 + tid]; \
        mn = fminf(mn, fminf(fminf(v.x, v.y), fminf(v.z, v.w))); \
        mx = fmaxf(mx, fmaxf(fmaxf(v.x, v.y), fmaxf(v.z, v.w))); \
        s += (v.x + v.y) + (v.z + v.w); \
        q += (v.x * v.x + v.y * v.y) + (v.z * v.z + v.w * v.w); }

    ISSUE(0) ISSUE(1) ISSUE(2) ISSUE(3) ISSUE(4) ISSUE(5) ISSUE(6) ISSUE(7)
    CONSUME(0, 7)  ISSUE(8)
    CONSUME(1, 7)  ISSUE(9)
    CONSUME(2, 7)  ISSUE(10)
    CONSUME(3, 7)  ISSUE(11)
    CONSUME(4, 7)  ISSUE(12)
    CONSUME(5, 7)  ISSUE(13)
    CONSUME(6, 7)  ISSUE(14)
    CONSUME(7, 7)  ISSUE(15)
    CONSUME(8, 7)
    CONSUME(9, 6)
    CONSUME(10, 5)
    CONSUME(11, 4)
    CONSUME(12, 3)
    CONSUME(13, 2)
    CONSUME(14, 1)
    CONSUME(15, 0)
#undef ISSUE
#undef CONSUME

#pragma unroll
    for (int o = 16; o > 0; o >>= 1) {
        mn = fminf(mn, __shfl_xor_sync(0xFFFFFFFFu, mn, o));
        mx = fmaxf(mx, __shfl_xor_sync(0xFFFFFFFFu, mx, o));
        s += __shfl_xor_sync(0xFFFFFFFFu, s, o);
        q += __shfl_xor_sync(0xFFFFFFFFu, q, o);
    }
    if (lane == 0) {
        wmn[wid] = mn; wmx[wid] = mx;
        wss[wid] = (double)s; wsq[wid] = (double)q;
    }
    __syncthreads();

    if (wid == 0) {
        float  fmn = (lane < 8) ? wmn[lane] :  FLT_MAX;
        float  fmx = (lane < 8) ? wmx[lane] : -FLT_MAX;
        double ds  = (lane < 8) ? wss[lane] : 0.0;
        double dq  = (lane < 8) ? wsq[lane] : 0.0;
#pragma unroll
        for (int o = 4; o > 0; o >>= 1) {
            fmn = fminf(fmn, __shfl_xor_sync(0xFFFFFFFFu, fmn, o));
            fmx = fmaxf(fmx, __shfl_xor_sync(0xFFFFFFFFu, fmx, o));
            ds += __shfl_xor_sync(0xFFFFFFFFu, ds, o);
            dq += __shfl_xor_sync(0xFFFFFFFFu, dq, o);
        }
        if (lane == 0) {
            g_pmin[blockIdx.x] = fmn;
            g_pmax[blockIdx.x] = fmx;
            g_psum[blockIdx.x] = ds;
            g_psq [blockIdx.x] = dq;
        }
    }

    // ---- last-block-done: finalize + tail ----
    __shared__ bool is_last;
    __threadfence();
    if (tid == 0) {
        unsigned int ticket = atomicAdd(&g_ctr, 1u);
        is_last = (ticket == RB - 1);
    }
    __syncthreads();
    if (!is_last) return;

    __shared__ float  smn2[256], smx2[256];
    __shared__ double ss2[256], sq2[256];
    {
        float  lmn =  FLT_MAX, lmx = -FLT_MAX;
        double ls = 0.0, lq = 0.0;
#pragma unroll
        for (int i = 0; i < 4; i++) {
            int k = tid + i * 256;
            lmn = fminf(lmn, g_pmin[k]);
            lmx = fmaxf(lmx, g_pmax[k]);
            ls += g_psum[k];
            lq += g_psq[k];
        }
        smn2[tid] = lmn; smx2[tid] = lmx; ss2[tid] = ls; sq2[tid] = lq;
    }
    __syncthreads();
    for (int o = 128; o > 0; o >>= 1) {
        if (tid < o) {
            smn2[tid] = fminf(smn2[tid], smn2[tid + o]);
            smx2[tid] = fmaxf(smx2[tid], smx2[tid + o]);
            ss2[tid] += ss2[tid + o];
            sq2[tid] += sq2[tid + o];
        }
        __syncthreads();
    }
    if (tid == 0) {
        double mn2 = (double)smn2[0];
        double mx2 = (double)smx2[0];
        double span = mx2 - mn2;
        const double N = (double)N_PIX;
        double S = ss2[0], Q = sq2[0];
        double meanx = S / N;
        double varx  = (Q - S * S / N) / (N - 1.0);
        double mean1 = (meanx - mn2) / span;
        double std1  = sqrt(varx) / span;
        double zmin  = (0.0 - mean1) / std1;
        double zmax  = (1.0 - mean1) / std1;
        double zspan = zmax - zmin;
        double A = 1.0 / (span * std1 * zspan);
        double B = (((0.0 - mn2) / span - mean1) / std1 - zmin) / zspan;
        g_AB[0] = (float)(A * 256.0);   // bin-ready
        g_AB[1] = (float)(B * 256.0);
        g_ctr = 0;                 // reset for next graph replay
    }
    if (tid < tail_n) tail_dst[tid] = (float)y[tid];   // y is int32
}

// bin = clamp((int)fmaf(v, A256, B256), 0, 255) — identical in hist & apply.
__device__ __forceinline__ int binof(float v, float A256, float B256)
{
    return min(max((int)fmaf(v, A256, B256), 0), 255);
}

#define BIASF 8388608.0f
__device__ __forceinline__ float u8biased(unsigned int packed, int sel)
{
    return __int_as_float(__byte_perm(packed, 0x4B000000, sel));
}

// ---------------------------------------------------------------------------
// hist item: tile t — 8 warp-private sub-histograms, clip/scan/residual/LUT,
// then publish tile-row completion (fence + counter).
// ---------------------------------------------------------------------------
__device__ void do_hist(int t, const float* __restrict__ x,
                        unsigned int* h, float* cs, int tid,
                        unsigned long long pl)
{
#pragma unroll
    for (int k = 0; k < 8; k++) h[k * BINS + tid] = 0;
    __syncthreads();

    float A = g_AB[0], B = g_AB[1];
    int bc = t >> 6;
    int ti = (t >> 3) & 7;
    int tj = t & 7;
    int row0 = ti * 128;
    int col0 = tj * 128;
    unsigned int* hw = h + (tid >> 5) * BINS;

    const float4* xp = (const float4*)(x + ((size_t)bc << 20));
#pragma unroll
    for (int it = 0; it < 16; it++) {
        int row   = row0 + it * 8 + (tid >> 5);
        int cidx4 = (row << 8) + (col0 >> 2) + (tid & 31);
        float4 v  = ld_x(&xp[cidx4], pl);
        atomicAdd(&hw[binof(v.x, A, B)], 1u);
        atomicAdd(&hw[binof(v.y, A, B)], 1u);
        atomicAdd(&hw[binof(v.z, A, B)], 1u);
        atomicAdd(&hw[binof(v.w, A, B)], 1u);
    }
    __syncthreads();

    unsigned int hv = 0;
#pragma unroll
    for (int k = 0; k < 8; k++) hv += h[k * BINS + tid];

    float v = fminf((float)hv, CLIPV);
    cs[tid] = v;
    __syncthreads();
#pragma unroll
    for (int off = 1; off < BINS; off <<= 1) {
        float add = (tid >= off) ? cs[tid - off] : 0.0f;
        __syncthreads();
        cs[tid] += add;
        __syncthreads();
    }
    float total = cs[BINS - 1];
    float resid = (16384.0f - total) * (1.0f / 256.0f);
    float lv = (cs[tid] + (float)(tid + 1) * resid) * (255.0f / 16384.0f);
    lv = floorf(fminf(fmaxf(lv, 0.0f), 255.0f));
    g_lut8[t * BINS + tid] = (unsigned char)lv;

    __threadfence();          // each thread's LUT byte visible device-wide
    __syncthreads();
    if (tid == 0) atomicAdd(&g_rowdone[bc * 8 + ti], 1u);
}

// ---------------------------------------------------------------------------
// apply item: (bc, band, quarter) — wait for the two needed LUT tile-rows,
// build packed slut, bilinear-apply 16 rows (ONE LDS.32 per pixel).
// x loads evict_last; out stores evict_first.
// ---------------------------------------------------------------------------
__device__ void do_apply(int a, const float4* __restrict__ x,
                         float4* __restrict__ out,
                         unsigned int* slut, int tid,
                         unsigned long long pl, unsigned long long pf)
{
    int bc   = a >> 6;
    int band = (a >> 2) & 15;
    int sub  = a & 3;
    int i0   = (band == 0) ? 0 : ((band - 1) >> 1);
    int i1   = min(i0 + 1, 7);

    if (tid == 0) {
        while (atomicAdd(&g_rowdone[bc * 8 + i0], 0u) < 8u) __nanosleep(64);
        while (atomicAdd(&g_rowdone[bc * 8 + i1], 0u) < 8u) __nanosleep(64);
    }
    __syncthreads();
    __threadfence();          // acquire: order LUT reads after counter observe

    const unsigned char* lb = g_lut8 + ((size_t)bc << 6) * BINS;
#pragma unroll
    for (int s = tid; s < 8 * BINS; s += 256) {
        int j0 = s >> 8, b = s & 255;
        int j1 = min(j0 + 1, 7);
        unsigned int v00 = __ldcg(&lb[(((i0 << 3) + j0) << 8) + b]);
        unsigned int v10 = __ldcg(&lb[(((i1 << 3) + j0) << 8) + b]);
        unsigned int v01 = __ldcg(&lb[(((i0 << 3) + j1) << 8) + b]);
        unsigned int v11 = __ldcg(&lb[(((i1 << 3) + j1) << 8) + b]);
        slut[s] = v00 | (v10 << 8) | (v01 << 16) | (v11 << 24);
    }
    __syncthreads();

    float A = g_AB[0], B = g_AB[1];

    float wx[4];
    int   jb[4];
#pragma unroll
    for (int p = 0; p < 4; p++) {
        int   col = (tid << 2) + p;
        float gj  = fminf(fmaxf((col + 0.5f) * (1.0f / 128.0f) - 0.5f, 0.0f), 7.0f);
        int   j0  = (int)gj;
        wx[p] = gj - (float)j0;
        jb[p] = j0 << 8;
    }

    int row_base = band * 64 + sub * 16;
    int f4_base  = (bc << 18) + (row_base << 8) + tid;

    float4 v = ld_x(&x[f4_base], pl);
#pragma unroll
    for (int it = 0; it < 16; it++) {
        float4 vn;
        if (it < 15) vn = ld_x(&x[f4_base + ((it + 1) << 8)], pl);

        int   row = row_base + it;
        float gi  = fminf(fmaxf((row + 0.5f) * (1.0f / 128.0f) - 0.5f, 0.0f), 7.0f);
        float wy  = gi - (float)i0;

        int bs[4];
        bs[0] = binof(v.x, A, B);
        bs[1] = binof(v.y, A, B);
        bs[2] = binof(v.z, A, B);
        bs[3] = binof(v.w, A, B);

        float r[4];
#pragma unroll
        for (int p = 0; p < 4; p++) {
            unsigned int packed = slut[jb[p] + bs[p]];
            float b00 = u8biased(packed, 0x7440);
            float b10 = u8biased(packed, 0x7441);
            float b01 = u8biased(packed, 0x7442);
            float b11 = u8biased(packed, 0x7443);
            float top = fmaf(wx[p], b01 - b00, b00 - BIASF);
            float bot = fmaf(wx[p], b11 - b10, b10 - BIASF);
            r[p] = fmaf(wy, bot - top, top) * (1.0f / 255.0f);
        }
        st_out(&out[f4_base + (it << 8)],
               make_float4(r[0], r[1], r[2], r[3]), pf);
        v = vn;
    }
}

// ---------------------------------------------------------------------------
// Kernel 2: fused hist+apply, dynamic work queue (R14). Items 0..1023 = hist
// tiles, 1024..2047 = apply quarter-bands; queue order makes apply spins
// deadlock-free. Last-exiting block resets queue state for the next replay.
// ---------------------------------------------------------------------------
__global__ void __launch_bounds__(256) k_fused(const float* __restrict__ x,
                                               float4* __restrict__ out)
{
    __shared__ unsigned int hbuf[8 * BINS];   // 8 KB: hist sub-hists / slut
    __shared__ float        cs[BINS];
    __shared__ int          s_item;

    int tid = threadIdx.x;
    unsigned long long pl = pol_evict_last();
    unsigned long long pf = pol_evict_first();

    for (;;) {
        if (tid == 0) s_item = (int)atomicAdd(&g_qhead, 1u);
        __syncthreads();
        int item = s_item;
        __syncthreads();
        if (item >= NITEMS) break;

        if (item < 1024) do_hist(item, x, hbuf, cs, tid, pl);
        else             do_apply(item - 1024, (const float4*)x, out, hbuf,
                                  tid, pl, pf);
    }

    if (tid == 0) {
        __threadfence();
        unsigned int tk = atomicAdd(&g_qdone, 1u);
        if (tk == FGRID - 1) {          // last exiter: all items complete
            g_qhead = 0;
            g_qdone = 0;
            for (int i = 0; i < 128; i++) g_rowdone[i] = 0;
        }
    }
}

extern "C" void kernel_launch(void* const* d_in, const int* in_sizes, int n_in,
                              void* d_out, int out_size)
{
    const float* x   = (const float*)d_in[0];
    const int*   y   = (n_in >= 2) ? (const int*)d_in[1] : nullptr;
    float*       out = (float*)d_out;

    int tail = out_size - N_PIX;
    if (tail < 0) tail = 0;

    k_reduce<<<RB, 256>>>((const float4*)x, y, out + N_PIX, tail);
    k_fused <<<FGRID, 256>>>(x, (float4*)out);
}

// round 16
// speedup vs baseline: 1.0462x; 1.0462x over previous
#include <cuda_runtime.h>
#include <cstdint>
#include <cfloat>

// Problem constants
#define N_PIX   16777216          // 16 * 1 * 1024 * 1024
#define NF4     4194304           // N_PIX / 4
#define RB      512               // reduction blocks (32 chunks each)
#define BINS    256
#define TILES   1024              // 16 images * 8 * 8
#define CLIPV   2560.0f           // max(int(40.0*16384//256),1)
#define FGRID   1024              // fused kernel grid
#define NITEMS  2048              // 1024 hist + 1024 apply

// Scratch (device globals only — no allocations allowed)
__device__ float         g_pmin[RB];
__device__ float         g_pmax[RB];
__device__ double        g_psum[RB];
__device__ double        g_psq [RB];
__device__ float         g_AB[2];     // A*256, B*256 (bin-ready affine)
__device__ unsigned int  g_ctr = 0;
__device__ unsigned char g_lut8[TILES * BINS];
__device__ unsigned int  g_qhead = 0;          // work-queue head
__device__ unsigned int  g_qdone = 0;          // exit tickets
__device__ unsigned int  g_rowdone[128];       // (image, tile-row) -> tiles done

__device__ __forceinline__ unsigned int smem_u32(const void* p)
{
    unsigned int a;
    asm("{ .reg .u64 t; cvta.to.shared.u64 t, %1; cvt.u32.u64 %0, t; }"
        : "=r"(a) : "l"(p));
    return a;
}

// ---------------------------------------------------------------------------
// Kernel 1: streaming min/max/sum/sumsq. 512 blocks x 256 thr x 32 chunks,
// 8-stage cp.async ring — 24 of 32 chunk-slots run in steady state (vs 8/16
// before) and the epilogue count is halved. Warp-shuffle epilogue; last block
// folds the 512 partials, computes A*256/B*256 (fp64 replica of the reference
// normalize -> standardize -> normalize collapse), writes the y tail.
// ---------------------------------------------------------------------------
__global__ void __launch_bounds__(256) k_reduce(const float4* __restrict__ x,
                                                const int* __restrict__ y,
                                                float* __restrict__ tail_dst,
                                                int tail_n)
{
    __shared__ float4 sbuf[8 * 256];        // 32 KB ring (8 stages)
    __shared__ float  wmn[8], wmx[8];
    __shared__ double wss[8], wsq[8];

    int tid  = threadIdx.x;
    int lane = tid & 31;
    int wid  = tid >> 5;
    int t    = blockIdx.x * 256 + tid;

    float mn =  FLT_MAX, mx = -FLT_MAX;
    float s = 0.0f, q = 0.0f;

#define ISSUE(c) { \
        unsigned int dst = smem_u32(&sbuf[((c) & 7) * 256 + tid]); \
        const float4* src = x + t + (c) * (RB * 256); \
        asm volatile("cp.async.cg.shared.global [%0], [%1], 16;" :: "r"(dst), "l"(src)); \
        asm volatile("cp.async.commit_group;"); }

#define CONSUME(c, W) { \
        asm volatile("cp.async.wait_group " #W ";" ::: "memory"); \
        float4 v = sbuf[((c) & 7) * 256 + tid]; \
        mn = fminf(mn, fminf(fminf(v.x, v.y), fminf(v.z, v.w))); \
        mx = fmaxf(mx, fmaxf(fmaxf(v.x, v.y), fmaxf(v.z, v.w))); \
        s += (v.x + v.y) + (v.z + v.w); \
        q += (v.x * v.x + v.y * v.y) + (v.z * v.z + v.w * v.w); }

    // prologue: fill the ring
    ISSUE(0) ISSUE(1) ISSUE(2) ISSUE(3) ISSUE(4) ISSUE(5) ISSUE(6) ISSUE(7)
    // steady state: consume c, issue c+8 (24 iterations)
#pragma unroll
    for (int c = 0; c < 24; c++) {
        CONSUME(c, 7)
        ISSUE(c + 8)
    }
    // drain
    CONSUME(24, 7)
    CONSUME(25, 6)
    CONSUME(26, 5)
    CONSUME(27, 4)
    CONSUME(28, 3)
    CONSUME(29, 2)
    CONSUME(30, 1)
    CONSUME(31, 0)
#undef ISSUE
#undef CONSUME

#pragma unroll
    for (int o = 16; o > 0; o >>= 1) {
        mn = fminf(mn, __shfl_xor_sync(0xFFFFFFFFu, mn, o));
        mx = fmaxf(mx, __shfl_xor_sync(0xFFFFFFFFu, mx, o));
        s += __shfl_xor_sync(0xFFFFFFFFu, s, o);
        q += __shfl_xor_sync(0xFFFFFFFFu, q, o);
    }
    if (lane == 0) {
        wmn[wid] = mn; wmx[wid] = mx;
        wss[wid] = (double)s; wsq[wid] = (double)q;
    }
    __syncthreads();

    if (wid == 0) {
        float  fmn = (lane < 8) ? wmn[lane] :  FLT_MAX;
        float  fmx = (lane < 8) ? wmx[lane] : -FLT_MAX;
        double ds  = (lane < 8) ? wss[lane] : 0.0;
        double dq  = (lane < 8) ? wsq[lane] : 0.0;
#pragma unroll
        for (int o = 4; o > 0; o >>= 1) {
            fmn = fminf(fmn, __shfl_xor_sync(0xFFFFFFFFu, fmn, o));
            fmx = fmaxf(fmx, __shfl_xor_sync(0xFFFFFFFFu, fmx, o));
            ds += __shfl_xor_sync(0xFFFFFFFFu, ds, o);
            dq += __shfl_xor_sync(0xFFFFFFFFu, dq, o);
        }
        if (lane == 0) {
            g_pmin[blockIdx.x] = fmn;
            g_pmax[blockIdx.x] = fmx;
            g_psum[blockIdx.x] = ds;
            g_psq [blockIdx.x] = dq;
        }
    }

    // ---- last-block-done: finalize + tail ----
    __shared__ bool is_last;
    __threadfence();
    if (tid == 0) {
        unsigned int ticket = atomicAdd(&g_ctr, 1u);
        is_last = (ticket == RB - 1);
    }
    __syncthreads();
    if (!is_last) return;

    __shared__ float  smn2[256], smx2[256];
    __shared__ double ss2[256], sq2[256];
    {
        float  lmn =  FLT_MAX, lmx = -FLT_MAX;
        double ls = 0.0, lq = 0.0;
#pragma unroll
        for (int i = 0; i < 2; i++) {
            int k = tid + i * 256;
            lmn = fminf(lmn, g_pmin[k]);
            lmx = fmaxf(lmx, g_pmax[k]);
            ls += g_psum[k];
            lq += g_psq[k];
        }
        smn2[tid] = lmn; smx2[tid] = lmx; ss2[tid] = ls; sq2[tid] = lq;
    }
    __syncthreads();
    for (int o = 128; o > 0; o >>= 1) {
        if (tid < o) {
            smn2[tid] = fminf(smn2[tid], smn2[tid + o]);
            smx2[tid] = fmaxf(smx2[tid], smx2[tid + o]);
            ss2[tid] += ss2[tid + o];
            sq2[tid] += sq2[tid + o];
        }
        __syncthreads();
    }
    if (tid == 0) {
        double mn2 = (double)smn2[0];
        double mx2 = (double)smx2[0];
        double span = mx2 - mn2;
        const double N = (double)N_PIX;
        double S = ss2[0], Q = sq2[0];
        double meanx = S / N;
        double varx  = (Q - S * S / N) / (N - 1.0);
        double mean1 = (meanx - mn2) / span;
        double std1  = sqrt(varx) / span;
        double zmin  = (0.0 - mean1) / std1;
        double zmax  = (1.0 - mean1) / std1;
        double zspan = zmax - zmin;
        double A = 1.0 / (span * std1 * zspan);
        double B = (((0.0 - mn2) / span - mean1) / std1 - zmin) / zspan;
        g_AB[0] = (float)(A * 256.0);   // bin-ready
        g_AB[1] = (float)(B * 256.0);
        g_ctr = 0;                 // reset for next graph replay
    }
    if (tid < tail_n) tail_dst[tid] = (float)y[tid];   // y is int32
}

// bin = clamp((int)fmaf(v, A256, B256), 0, 255) — identical in hist & apply.
__device__ __forceinline__ int binof(float v, float A256, float B256)
{
    return min(max((int)fmaf(v, A256, B256), 0), 255);
}

#define BIASF 8388608.0f
__device__ __forceinline__ float u8biased(unsigned int packed, int sel)
{
    return __int_as_float(__byte_perm(packed, 0x4B000000, sel));
}

// ---------------------------------------------------------------------------
// hist item: tile t — 8 warp-private sub-histograms, clip/scan/residual/LUT,
// then publish tile-row completion (fence + counter).
// ---------------------------------------------------------------------------
__device__ void do_hist(int t, const float* __restrict__ x,
                        unsigned int* h, float* cs, int tid)
{
#pragma unroll
    for (int k = 0; k < 8; k++) h[k * BINS + tid] = 0;
    __syncthreads();

    float A = g_AB[0], B = g_AB[1];
    int bc = t >> 6;
    int ti = (t >> 3) & 7;
    int tj = t & 7;
    int row0 = ti * 128;
    int col0 = tj * 128;
    unsigned int* hw = h + (tid >> 5) * BINS;

    const float4* xp = (const float4*)(x + ((size_t)bc << 20));
#pragma unroll
    for (int it = 0; it < 16; it++) {
        int row   = row0 + it * 8 + (tid >> 5);
        int cidx4 = (row << 8) + (col0 >> 2) + (tid & 31);
        float4 v  = xp[cidx4];
        atomicAdd(&hw[binof(v.x, A, B)], 1u);
        atomicAdd(&hw[binof(v.y, A, B)], 1u);
        atomicAdd(&hw[binof(v.z, A, B)], 1u);
        atomicAdd(&hw[binof(v.w, A, B)], 1u);
    }
    __syncthreads();

    unsigned int hv = 0;
#pragma unroll
    for (int k = 0; k < 8; k++) hv += h[k * BINS + tid];

    float v = fminf((float)hv, CLIPV);
    cs[tid] = v;
    __syncthreads();
#pragma unroll
    for (int off = 1; off < BINS; off <<= 1) {
        float add = (tid >= off) ? cs[tid - off] : 0.0f;
        __syncthreads();
        cs[tid] += add;
        __syncthreads();
    }
    float total = cs[BINS - 1];
    float resid = (16384.0f - total) * (1.0f / 256.0f);
    float lv = (cs[tid] + (float)(tid + 1) * resid) * (255.0f / 16384.0f);
    lv = floorf(fminf(fmaxf(lv, 0.0f), 255.0f));
    g_lut8[t * BINS + tid] = (unsigned char)lv;

    __threadfence();          // each thread's LUT byte visible device-wide
    __syncthreads();
    if (tid == 0) atomicAdd(&g_rowdone[bc * 8 + ti], 1u);
}

// ---------------------------------------------------------------------------
// apply item: (bc, band, quarter) — wait for the two needed LUT tile-rows,
// build packed slut, bilinear-apply 16 rows (ONE LDS.32 per pixel).
// ---------------------------------------------------------------------------
__device__ void do_apply(int a, const float4* __restrict__ x,
                         float4* __restrict__ out,
                         unsigned int* slut, int tid)
{
    int bc   = a >> 6;
    int band = (a >> 2) & 15;
    int sub  = a & 3;
    int i0   = (band == 0) ? 0 : ((band - 1) >> 1);
    int i1   = min(i0 + 1, 7);

    if (tid == 0) {
        while (atomicAdd(&g_rowdone[bc * 8 + i0], 0u) < 8u) __nanosleep(64);
        while (atomicAdd(&g_rowdone[bc * 8 + i1], 0u) < 8u) __nanosleep(64);
    }
    __syncthreads();
    __threadfence();          // acquire: order LUT reads after counter observe

    const unsigned char* lb = g_lut8 + ((size_t)bc << 6) * BINS;
#pragma unroll
    for (int s = tid; s < 8 * BINS; s += 256) {
        int j0 = s >> 8, b = s & 255;
        int j1 = min(j0 + 1, 7);
        unsigned int v00 = __ldcg(&lb[(((i0 << 3) + j0) << 8) + b]);
        unsigned int v10 = __ldcg(&lb[(((i1 << 3) + j0) << 8) + b]);
        unsigned int v01 = __ldcg(&lb[(((i0 << 3) + j1) << 8) + b]);
        unsigned int v11 = __ldcg(&lb[(((i1 << 3) + j1) << 8) + b]);
        slut[s] = v00 | (v10 << 8) | (v01 << 16) | (v11 << 24);
    }
    __syncthreads();

    float A = g_AB[0], B = g_AB[1];

    float wx[4];
    int   jb[4];
#pragma unroll
    for (int p = 0; p < 4; p++) {
        int   col = (tid << 2) + p;
        float gj  = fminf(fmaxf((col + 0.5f) * (1.0f / 128.0f) - 0.5f, 0.0f), 7.0f);
        int   j0  = (int)gj;
        wx[p] = gj - (float)j0;
        jb[p] = j0 << 8;
    }

    int row_base = band * 64 + sub * 16;
    int f4_base  = (bc << 18) + (row_base << 8) + tid;

    float4 v = x[f4_base];
#pragma unroll
    for (int it = 0; it < 16; it++) {
        float4 vn;
        if (it < 15) vn = x[f4_base + ((it + 1) << 8)];

        int   row = row_base + it;
        float gi  = fminf(fmaxf((row + 0.5f) * (1.0f / 128.0f) - 0.5f, 0.0f), 7.0f);
        float wy  = gi - (float)i0;

        int bs[4];
        bs[0] = binof(v.x, A, B);
        bs[1] = binof(v.y, A, B);
        bs[2] = binof(v.z, A, B);
        bs[3] = binof(v.w, A, B);

        float r[4];
#pragma unroll
        for (int p = 0; p < 4; p++) {
            unsigned int packed = slut[jb[p] + bs[p]];
            float b00 = u8biased(packed, 0x7440);
            float b10 = u8biased(packed, 0x7441);
            float b01 = u8biased(packed, 0x7442);
            float b11 = u8biased(packed, 0x7443);
            float top = fmaf(wx[p], b01 - b00, b00 - BIASF);
            float bot = fmaf(wx[p], b11 - b10, b10 - BIASF);
            r[p] = fmaf(wy, bot - top, top) * (1.0f / 255.0f);
        }
        __stcs(&out[f4_base + (it << 8)], make_float4(r[0], r[1], r[2], r[3]));
        v = vn;
    }
}

// ---------------------------------------------------------------------------
// Kernel 2: fused hist+apply, dynamic work queue (R14-proven). Items
// 0..1023 = hist tiles, 1024..2047 = apply quarter-bands; queue order makes
// apply spins deadlock-free. Last-exiting block resets queue state.
// ---------------------------------------------------------------------------
__global__ void __launch_bounds__(256) k_fused(const float* __restrict__ x,
                                               float4* __restrict__ out)
{
    __shared__ unsigned int hbuf[8 * BINS];   // 8 KB: hist sub-hists / slut
    __shared__ float        cs[BINS];
    __shared__ int          s_item;

    int tid = threadIdx.x;

    for (;;) {
        if (tid == 0) s_item = (int)atomicAdd(&g_qhead, 1u);
        __syncthreads();
        int item = s_item;
        __syncthreads();
        if (item >= NITEMS) break;

        if (item < 1024) do_hist(item, x, hbuf, cs, tid);
        else             do_apply(item - 1024, (const float4*)x, out, hbuf, tid);
    }

    if (tid == 0) {
        __threadfence();
        unsigned int tk = atomicAdd(&g_qdone, 1u);
        if (tk == FGRID - 1) {          // last exiter: all items complete
            g_qhead = 0;
            g_qdone = 0;
            for (int i = 0; i < 128; i++) g_rowdone[i] = 0;
        }
    }
}

extern "C" void kernel_launch(void* const* d_in, const int* in_sizes, int n_in,
                              void* d_out, int out_size)
{
    const float* x   = (const float*)d_in[0];
    const int*   y   = (n_in >= 2) ? (const int*)d_in[1] : nullptr;
    float*       out = (float*)d_out;

    int tail = out_size - N_PIX;
    if (tail < 0) tail = 0;

    k_reduce<<<RB, 256>>>((const float4*)x, y, out + N_PIX, tail);
    k_fused <<<FGRID, 256>>>(x, (float4*)out);
}